// round 3
// baseline (speedup 1.0000x reference)
#include <cuda_runtime.h>
#include <cuda_bf16.h>

#define N_PRED 2048
#define T_RUNS 16
#define M_BOX  2048
#define EPS_F  1e-7f

#define GB      16
#define NBINS   (GB*GB)
#define BIN_ORG (-28.0f)
#define BIN_INV (1.0f/42.0f)
#define WH_MAX  55.0f          // box w,h in [5,55)

// ---- device scratch (no allocations allowed) ----
__device__ float4 g_sbox[T_RUNS][M_BOX];      // binned boxes (x1,y1,x2,y2)
__device__ float  g_snarea[T_RUNS][M_BOX];    // -(areaB), binned order
__device__ int    g_bstart[T_RUNS][NBINS+1];  // bin prefix offsets per run
__device__ float4 g_pbox[N_PRED];             // pred boxes in bin-sorted order
__device__ int    g_perm[N_PRED];             // sorted slot -> original pred idx

__device__ __forceinline__ int bin1d(float v) {
    int b = (int)floorf((v - BIN_ORG) * BIN_INV);
    return min(max(b, 0), GB - 1);
}

// ---------------------------------------------------------------------------
// prep: blocks 0..15 counting-sort run t's boxes; block 16 sorts preds and
// zeroes out. 256 threads == NBINS.
// ---------------------------------------------------------------------------
__global__ __launch_bounds__(256)
void prep_kernel(const float* __restrict__ pred,
                 const float* __restrict__ dropout_preds,
                 float* __restrict__ out)
{
    __shared__ int cnt[NBINS];
    __shared__ int wsum[8];
    const int tid  = threadIdx.x;
    const int lane = tid & 31, wid = tid >> 5;
    const bool is_box_block = (blockIdx.x < T_RUNS);

    cnt[tid] = 0;
    __syncthreads();

    // ---- count ----
    float4 box[8];
    int    bin[8];
    if (is_box_block) {
        const float* src = dropout_preds + (size_t)blockIdx.x * M_BOX * 6;
        #pragma unroll
        for (int k = 0; k < M_BOX / 256; ++k) {
            const float* b6 = src + (tid + k * 256) * 6;
            box[k] = make_float4(b6[0], b6[1], b6[2], b6[3]);
            bin[k] = bin1d(box[k].y) * GB + bin1d(box[k].x);
            atomicAdd(&cnt[bin[k]], 1);
        }
    } else {
        #pragma unroll
        for (int k = 0; k < N_PRED / 256; ++k) {
            int p = tid + k * 256;
            const float* a = pred + p * 6;
            box[k] = make_float4(a[0], a[1], a[2], a[3]);
            bin[k] = bin1d(box[k].y) * GB + bin1d(box[k].x);
            atomicAdd(&cnt[bin[k]], 1);
            out[p] = 0.0f;        // out is poisoned; zero before match
        }
    }
    __syncthreads();

    // ---- exclusive scan over 256 bins (warp shfl + 8-way combine) ----
    int v = cnt[tid];
    int inc = v;
    #pragma unroll
    for (int o = 1; o < 32; o <<= 1) {
        int n = __shfl_up_sync(0xffffffffu, inc, o);
        if (lane >= o) inc += n;
    }
    if (lane == 31) wsum[wid] = inc;
    __syncthreads();
    if (wid == 0) {
        int w = (lane < 8) ? wsum[lane] : 0;
        int wi = w;
        #pragma unroll
        for (int o = 1; o < 8; o <<= 1) {
            int n = __shfl_up_sync(0xffffffffu, wi, o);
            if (lane >= o) wi += n;
        }
        if (lane < 8) wsum[lane] = wi - w;   // exclusive warp offsets
    }
    __syncthreads();
    const int start = inc - v + wsum[wid];   // exclusive prefix for this bin
    cnt[tid] = start;                        // running scatter offsets
    __syncthreads();

    // ---- scatter ----
    if (is_box_block) {
        const int t = blockIdx.x;
        g_bstart[t][tid] = start;
        if (tid == 0) g_bstart[t][NBINS] = M_BOX;
        #pragma unroll
        for (int k = 0; k < M_BOX / 256; ++k) {
            int pos = atomicAdd(&cnt[bin[k]], 1);
            g_sbox[t][pos]   = box[k];
            g_snarea[t][pos] = -((box[k].z - box[k].x) * (box[k].w - box[k].y));
        }
    } else {
        #pragma unroll
        for (int k = 0; k < N_PRED / 256; ++k) {
            int pos = atomicAdd(&cnt[bin[k]], 1);
            g_pbox[pos] = box[k];
            g_perm[pos] = tid + k * 256;
        }
    }
}

// ---------------------------------------------------------------------------
// match: 1024 warps, one warp = 32 bin-sorted preds x one run. Warp-uniform
// union window -> fully broadcast global loads, no smem, no divergence.
// Scanning extra boxes is safe: outside-window boxes have inter<=0 < thr.
// ---------------------------------------------------------------------------
__global__ __launch_bounds__(128)
void match_kernel(float* __restrict__ out)
{
    const int gtid = blockIdx.x * 128 + threadIdx.x;
    const int gw   = gtid >> 5, lane = gtid & 31;
    const int t    = gw >> 6;                 // 64 warps per run
    const int slot = ((gw & 63) << 5) + lane;

    const float4 a  = g_pbox[slot];
    const int    p  = g_perm[slot];
    const float thr = (a.z - a.x) * (a.w - a.y) + EPS_F;

    int xb0 = bin1d(a.x - WH_MAX), xb1 = bin1d(a.z);
    int yb0 = bin1d(a.y - WH_MAX), yb1 = bin1d(a.w);
    xb0 = __reduce_min_sync(0xffffffffu, xb0);
    xb1 = __reduce_max_sync(0xffffffffu, xb1);
    yb0 = __reduce_min_sync(0xffffffffu, yb0);
    yb1 = __reduce_max_sync(0xffffffffu, yb1);

    const float4* __restrict__ boxes = g_sbox[t];
    const float*  __restrict__ nare  = g_snarea[t];
    const int*    __restrict__ bs    = g_bstart[t];

    float best = -1e30f;
    for (int yb = yb0; yb <= yb1; ++yb) {
        const int s = __ldg(&bs[yb * GB + xb0]);
        const int e = __ldg(&bs[yb * GB + xb1 + 1]);
        #pragma unroll 4
        for (int m = s; m < e; ++m) {
            float4 b  = boxes[m];              // warp-broadcast LDG.128
            float na  = nare[m];
            float ix1 = fmaxf(a.x, b.x);
            float iy1 = fmaxf(a.y, b.y);
            float ix2 = fminf(a.z, b.z);
            float iy2 = fminf(a.w, b.w);
            float dx  = fmaxf(ix2 - ix1, 0.0f);
            float dy  = iy2 - iy1;             // no clamp: dy<0 => inter<=0 < thr
            best = fmaxf(best, fmaf(3.0f, dx * dy, na));
        }
        if (__all_sync(0xffffffffu, best > thr)) break;
    }

    // 16 adds of exactly 1/16 are order-independent & exact -> deterministic
    if (best > thr) atomicAdd(&out[p], 1.0f / (float)T_RUNS);
}

extern "C" void kernel_launch(void* const* d_in, const int* in_sizes, int n_in,
                              void* d_out, int out_size)
{
    const float* pred          = (const float*)d_in[0]; // [2048, 6]
    const float* dropout_preds = (const float*)d_in[1]; // [16, 2048, 6]
    // d_in[2] (dropout_cls_confs) unused by the reference computation.
    float* out = (float*)d_out;                          // [2048]

    prep_kernel<<<T_RUNS + 1, 256>>>(pred, dropout_preds, out);
    match_kernel<<<(N_PRED * T_RUNS / 32) / 4, 128>>>(out);
}

// round 4
// speedup vs baseline: 2.7743x; 2.7743x over previous
#include <cuda_runtime.h>
#include <cuda_bf16.h>

#define N_PRED 2048
#define T_RUNS 16
#define M_BOX  2048
#define EPS_F  1e-7f

#define GB      16
#define NBINS   (GB*GB)
#define BIN_ORG (-28.0f)
#define BIN_INV (1.0f/42.0f)
#define WH_MAX  55.0f          // box w,h in [5,55)
#define CAP     1280           // smem slab capacity (5 rows avg ~640)

// ---- device scratch (no allocations allowed) ----
__device__ float4 g_sbox[T_RUNS][M_BOX];      // binned boxes (x1,y1,x2,y2)
__device__ float  g_snarea[T_RUNS][M_BOX];    // -(areaB), binned order
__device__ int    g_bstart[T_RUNS][NBINS+1];  // box bin prefix offsets per run
__device__ float4 g_pbox[N_PRED];             // pred boxes, bin-sorted
__device__ int    g_perm[N_PRED];             // sorted slot -> original pred idx
__device__ int    g_pstart[NBINS+1];          // pred bin prefix offsets

__device__ __forceinline__ int bin1d(float v) {
    int b = (int)floorf((v - BIN_ORG) * BIN_INV);
    return min(max(b, 0), GB - 1);
}

// ---------------------------------------------------------------------------
// prep: blocks 0..15 counting-sort run t's boxes; block 16 sorts preds,
// writes g_pstart, zeroes out. 256 threads == NBINS.
// ---------------------------------------------------------------------------
__global__ __launch_bounds__(256)
void prep_kernel(const float* __restrict__ pred,
                 const float* __restrict__ dropout_preds,
                 float* __restrict__ out)
{
    __shared__ int cnt[NBINS];
    __shared__ int wsum[8];
    const int tid  = threadIdx.x;
    const int lane = tid & 31, wid = tid >> 5;
    const bool is_box_block = (blockIdx.x < T_RUNS);

    cnt[tid] = 0;
    __syncthreads();

    // ---- count ----
    float4 box[8];
    int    bin[8];
    if (is_box_block) {
        const float* src = dropout_preds + (size_t)blockIdx.x * M_BOX * 6;
        #pragma unroll
        for (int k = 0; k < M_BOX / 256; ++k) {
            const float* b6 = src + (tid + k * 256) * 6;
            box[k] = make_float4(b6[0], b6[1], b6[2], b6[3]);
            bin[k] = bin1d(box[k].y) * GB + bin1d(box[k].x);
            atomicAdd(&cnt[bin[k]], 1);
        }
    } else {
        #pragma unroll
        for (int k = 0; k < N_PRED / 256; ++k) {
            int p = tid + k * 256;
            const float* a = pred + p * 6;
            box[k] = make_float4(a[0], a[1], a[2], a[3]);
            bin[k] = bin1d(box[k].y) * GB + bin1d(box[k].x);
            atomicAdd(&cnt[bin[k]], 1);
            out[p] = 0.0f;        // out is poisoned; zero before match
        }
    }
    __syncthreads();

    // ---- exclusive scan over 256 bins (shfl + 8-way combine) ----
    int v = cnt[tid];
    int inc = v;
    #pragma unroll
    for (int o = 1; o < 32; o <<= 1) {
        int n = __shfl_up_sync(0xffffffffu, inc, o);
        if (lane >= o) inc += n;
    }
    if (lane == 31) wsum[wid] = inc;
    __syncthreads();
    if (wid == 0) {
        int w = (lane < 8) ? wsum[lane] : 0;
        int wi = w;
        #pragma unroll
        for (int o = 1; o < 8; o <<= 1) {
            int n = __shfl_up_sync(0xffffffffu, wi, o);
            if (lane >= o) wi += n;
        }
        if (lane < 8) wsum[lane] = wi - w;   // exclusive warp offsets
    }
    __syncthreads();
    const int start = inc - v + wsum[wid];
    cnt[tid] = start;
    __syncthreads();

    // ---- scatter ----
    if (is_box_block) {
        const int t = blockIdx.x;
        g_bstart[t][tid] = start;
        if (tid == 0) g_bstart[t][NBINS] = M_BOX;
        #pragma unroll
        for (int k = 0; k < M_BOX / 256; ++k) {
            int pos = atomicAdd(&cnt[bin[k]], 1);
            g_sbox[t][pos]   = box[k];
            g_snarea[t][pos] = -((box[k].z - box[k].x) * (box[k].w - box[k].y));
        }
    } else {
        g_pstart[tid] = start;
        if (tid == 0) g_pstart[NBINS] = N_PRED;
        #pragma unroll
        for (int k = 0; k < N_PRED / 256; ++k) {
            int pos = atomicAdd(&cnt[bin[k]], 1);
            g_pbox[pos] = box[k];
            g_perm[pos] = tid + k * 256;
        }
    }
}

// ---------------------------------------------------------------------------
// match: CTA = (half, pred-y-row yr, run t). Loads the contiguous box slab
// for rows [yr-2, yr+2] into smem (~640 boxes), then each thread scans its
// pred's exact bin window. Outside-window boxes can't match (inter <= 0).
// ---------------------------------------------------------------------------
__global__ __launch_bounds__(128)
void match_kernel(float* __restrict__ out)
{
    __shared__ float4 sbox[CAP];
    __shared__ float  snarea[CAP];
    __shared__ int    sbs[5 * GB + 1];

    const int tid  = threadIdx.x;
    const int half = blockIdx.x;
    const int yr   = blockIdx.y;
    const int t    = blockIdx.z;

    const int r0 = max(yr - 2, 0), r1 = min(yr + 2, GB - 1);
    const int bin_lo = r0 * GB, bin_hi = (r1 + 1) * GB;
    const int nbs = bin_hi - bin_lo + 1;

    const int base = __ldg(&g_bstart[t][bin_lo]);
    const int endi = __ldg(&g_bstart[t][bin_hi]);
    const int n    = endi - base;

    for (int i = tid; i < nbs; i += 128) sbs[i] = g_bstart[t][bin_lo + i];
    const int ncap = min(n, CAP);
    for (int i = tid; i < ncap; i += 128) {
        sbox[i]   = g_sbox[t][base + i];
        snarea[i] = g_snarea[t][base + i];
    }
    __syncthreads();

    // this CTA's pred slots: half of row yr's contiguous sorted range
    const int ps = g_pstart[yr * GB], pe = g_pstart[(yr + 1) * GB];
    const int mid = (ps + pe) >> 1;
    const int seg_s = half ? mid : ps;
    const int seg_e = half ? pe  : mid;
    const bool all_smem = (n <= CAP);   // always true for uniform data

    for (int slot = seg_s + tid; slot < seg_e; slot += 128) {
        const float4 a  = g_pbox[slot];
        const int    p  = g_perm[slot];
        const float thr = (a.z - a.x) * (a.w - a.y) + EPS_F;

        const int xb0 = bin1d(a.x - WH_MAX), xb1 = bin1d(a.z);
        const int yb0 = max(bin1d(a.y - WH_MAX), r0);
        const int yb1 = min(bin1d(a.w), r1);

        float best = -1e30f;
        if (all_smem) {
            for (int yb = yb0; yb <= yb1; ++yb) {
                const int rb = yb * GB - bin_lo;
                const int s  = sbs[rb + xb0] - base;
                const int e  = sbs[rb + xb1 + 1] - base;
                #pragma unroll 4
                for (int m = s; m < e; ++m) {
                    float4 b  = sbox[m];
                    float ix1 = fmaxf(a.x, b.x);
                    float iy1 = fmaxf(a.y, b.y);
                    float ix2 = fminf(a.z, b.z);
                    float iy2 = fminf(a.w, b.w);
                    float dx  = fmaxf(ix2 - ix1, 0.0f);
                    float dy  = iy2 - iy1;        // dy<0 => inter<=0 < thr
                    best = fmaxf(best, fmaf(3.0f, dx * dy, snarea[m]));
                }
                if (best > thr) break;
            }
        } else {                                   // safety fallback
            for (int yb = yb0; yb <= yb1; ++yb) {
                const int rb = yb * GB - bin_lo;
                const int s  = sbs[rb + xb0];
                const int e  = sbs[rb + xb1 + 1];
                for (int m = s; m < e; ++m) {
                    float4 b  = g_sbox[t][m];
                    float na  = g_snarea[t][m];
                    float ix1 = fmaxf(a.x, b.x);
                    float iy1 = fmaxf(a.y, b.y);
                    float ix2 = fminf(a.z, b.z);
                    float iy2 = fminf(a.w, b.w);
                    float dx  = fmaxf(ix2 - ix1, 0.0f);
                    float dy  = iy2 - iy1;
                    best = fmaxf(best, fmaf(3.0f, dx * dy, na));
                }
                if (best > thr) break;
            }
        }

        // 16 adds of exactly 1/16: order-independent & exact -> deterministic
        if (best > thr) atomicAdd(&out[p], 1.0f / (float)T_RUNS);
    }
}

extern "C" void kernel_launch(void* const* d_in, const int* in_sizes, int n_in,
                              void* d_out, int out_size)
{
    const float* pred          = (const float*)d_in[0]; // [2048, 6]
    const float* dropout_preds = (const float*)d_in[1]; // [16, 2048, 6]
    // d_in[2] (dropout_cls_confs) unused by the reference computation.
    float* out = (float*)d_out;                          // [2048]

    prep_kernel<<<T_RUNS + 1, 256>>>(pred, dropout_preds, out);
    match_kernel<<<dim3(2, GB, T_RUNS), 128>>>(out);
}